// round 7
// baseline (speedup 1.0000x reference)
#include <cuda_runtime.h>
#include <cstdint>

// 2x2 Haar inverse reconstruction:
//   x: (32, 4, 512, 512) f32  ->  out: (32, 1, 1024, 1024) f32
//   L0=R*a+R*b; L1=R*a-R*b; H0=R*c+R*d; H1=R*c-R*d
//   out[2h,2w]=R*(L0+H0)  out[2h,2w+1]=R*(L0-H0)
//   out[2h+1,2w]=R*(L1+H1)  out[2h+1,2w+1]=R*(L1-H1)
//
// R7: reads = direct LDG.128.cs (best config, R5). Writes = bulk stores.
// Each CTA handles TWO row-pairs with double-buffered 16KB staging:
// store of pair0 overlaps load/compute of pair1; the two stores cover
// 32KB of contiguous output.

#define RCONST 0.70710678118654752440f

static constexpr int S = 512;     // input spatial
static constexpr int NIMG = 32;   // batch

__device__ __forceinline__ void haar4(float a, float b, float c, float d,
                                      float& o00, float& o01, float& o10, float& o11) {
    float l0 = RCONST * a + RCONST * b;
    float l1 = RCONST * a - RCONST * b;
    float h0 = RCONST * c + RCONST * d;
    float h1 = RCONST * c - RCONST * d;
    o00 = RCONST * l0 + RCONST * h0;
    o01 = RCONST * l0 - RCONST * h0;
    o10 = RCONST * l1 + RCONST * h1;
    o11 = RCONST * l1 - RCONST * h1;
}

__device__ __forceinline__ uint32_t smem_u32(const void* p) {
    uint32_t a;
    asm("{ .reg .u64 t; cvta.to.shared.u64 t, %1; cvt.u32.u64 %0, t; }"
        : "=r"(a) : "l"(p));
    return a;
}

__global__ __launch_bounds__(256)
void haar_recon_kernel(const float* __restrict__ x, float* __restrict__ out) {
    // two staging buffers: 4 output rows x 1024 floats = 16KB each
    __shared__ alignas(16) float sout[2][4 * 2 * S];

    unsigned t  = threadIdx.x;
    unsigned b  = blockIdx.x;
    unsigned wq = t & 127;        // float4 index within input row
    unsigned hl = (t >> 7) & 1;   // 0/1: which of the 2 input rows in the pair
    unsigned k2 = b & 127;        // row-quad index: input rows 4*k2 .. 4*k2+3
    unsigned n  = b >> 7;         // image

    const size_t cs4 = (size_t)S * S / 4;   // channel stride in float4

    #pragma unroll
    for (int p = 0; p < 2; p++) {
        unsigned h = 4 * k2 + 2 * p + hl;
        const float4* base =
            (const float4*)(x + (size_t)n * 4 * S * S + (size_t)h * S) + wq;

        // 4 independent 128-bit streaming loads (MLP=4)
        float4 a  = __ldcs(base);
        float4 bb = __ldcs(base + cs4);
        float4 c  = __ldcs(base + 2 * cs4);
        float4 d  = __ldcs(base + 3 * cs4);

        float4 r0a, r0b, r1a, r1b;
        haar4(a.x, bb.x, c.x, d.x, r0a.x, r0a.y, r1a.x, r1a.y);
        haar4(a.y, bb.y, c.y, d.y, r0a.z, r0a.w, r1a.z, r1a.w);
        haar4(a.z, bb.z, c.z, d.z, r0b.x, r0b.y, r1b.x, r1b.y);
        haar4(a.w, bb.w, c.w, d.w, r0b.z, r0b.w, r1b.z, r1b.w);

        float4* srow0 = (float4*)(sout[p] + (2 * hl)     * (2 * S)) + 2 * wq;
        float4* srow1 = (float4*)(sout[p] + (2 * hl + 1) * (2 * S)) + 2 * wq;
        srow0[0] = r0a;
        srow0[1] = r0b;
        srow1[0] = r1a;
        srow1[1] = r1b;

        __syncthreads();

        if (t == 0) {
            asm volatile("fence.proxy.async.shared::cta;" ::: "memory");
            // output rows 8*k2 + 4*p .. +4  (16KB contiguous)
            float* gdst = out + ((size_t)n * 2 * S + (size_t)(8 * k2 + 4 * p)) * (2 * S);
            asm volatile(
                "cp.async.bulk.global.shared::cta.bulk_group [%0], [%1], %2;"
                :: "l"(gdst), "r"(smem_u32(sout[p])),
                   "r"((unsigned)(4 * 2 * S * sizeof(float)))
                : "memory");
            asm volatile("cp.async.bulk.commit_group;" ::: "memory");
        }
        // NOTE: no wait here — store p=0 drains while pair p=1 loads/computes.
    }

    if (t == 0) {
        asm volatile("cp.async.bulk.wait_group 0;" ::: "memory");
    }
}

extern "C" void kernel_launch(void* const* d_in, const int* in_sizes, int n_in,
                              void* d_out, int out_size) {
    const float* x = (const float*)d_in[0];
    float* out = (float*)d_out;
    // one CTA per (n, row-quad): 32 * 128 = 4096 CTAs
    haar_recon_kernel<<<NIMG * (S / 4), 256>>>(x, out);
}

// round 9
// speedup vs baseline: 1.0901x; 1.0901x over previous
#include <cuda_runtime.h>
#include <cstdint>

// 2x2 Haar inverse reconstruction:
//   x: (32, 4, 512, 512) f32  ->  out: (32, 1, 1024, 1024) f32
//   L0=R*a+R*b; L1=R*a-R*b; H0=R*c+R*d; H1=R*c-R*d
//   out[2h,2w]=R*(L0+H0)  out[2h,2w+1]=R*(L0-H0)
//   out[2h+1,2w]=R*(L1+H1)  out[2h+1,2w+1]=R*(L1-H1)
//
// R8 (rerun; prior attempt hit an infra failure): R5 recipe (direct
// LDG.128.cs reads + bulk store) at 512 threads/CTA. One CTA = row-quad
// (4 input rows) -> 8 contiguous output rows staged in 32KB smem, written
// by a single 32KB cp.async.bulk. smem/thread identical to R5 (64B)
// -> 4 CTAs/SM, 100% theoretical occupancy.

#define RCONST 0.70710678118654752440f

static constexpr int S = 512;     // input spatial
static constexpr int NIMG = 32;   // batch

__device__ __forceinline__ void haar4(float a, float b, float c, float d,
                                      float& o00, float& o01, float& o10, float& o11) {
    float l0 = RCONST * a + RCONST * b;
    float l1 = RCONST * a - RCONST * b;
    float h0 = RCONST * c + RCONST * d;
    float h1 = RCONST * c - RCONST * d;
    o00 = RCONST * l0 + RCONST * h0;
    o01 = RCONST * l0 - RCONST * h0;
    o10 = RCONST * l1 + RCONST * h1;
    o11 = RCONST * l1 - RCONST * h1;
}

__device__ __forceinline__ uint32_t smem_u32(const void* p) {
    uint32_t a;
    asm("{ .reg .u64 t; cvta.to.shared.u64 t, %1; cvt.u32.u64 %0, t; }"
        : "=r"(a) : "l"(p));
    return a;
}

__global__ __launch_bounds__(512)
void haar_recon_kernel(const float* __restrict__ x, float* __restrict__ out) {
    // 8 output rows x 1024 floats = 32KB
    __shared__ alignas(16) float sout[8 * 2 * S];

    unsigned t  = threadIdx.x;
    unsigned b  = blockIdx.x;
    unsigned wq = t & 127;        // float4 index within input row
    unsigned hl = t >> 7;         // 0..3: input row within the quad
    unsigned k2 = b & 127;        // row-quad index: input rows 4*k2 .. 4*k2+3
    unsigned n  = b >> 7;         // image
    unsigned h  = 4 * k2 + hl;

    const size_t cs4 = (size_t)S * S / 4;   // channel stride in float4
    const float4* base = (const float4*)(x + (size_t)n * 4 * S * S + (size_t)h * S) + wq;

    // 4 independent 128-bit streaming loads (MLP=4)
    float4 a  = __ldcs(base);
    float4 bb = __ldcs(base + cs4);
    float4 c  = __ldcs(base + 2 * cs4);
    float4 d  = __ldcs(base + 3 * cs4);

    float4 r0a, r0b, r1a, r1b;
    haar4(a.x, bb.x, c.x, d.x, r0a.x, r0a.y, r1a.x, r1a.y);
    haar4(a.y, bb.y, c.y, d.y, r0a.z, r0a.w, r1a.z, r1a.w);
    haar4(a.z, bb.z, c.z, d.z, r0b.x, r0b.y, r1b.x, r1b.y);
    haar4(a.w, bb.w, c.w, d.w, r0b.z, r0b.w, r1b.z, r1b.w);

    // stage local rows (2*hl, 2*hl+1), cols [8wq, 8wq+8)
    float4* srow0 = (float4*)(sout + (2 * hl)     * (2 * S)) + 2 * wq;
    float4* srow1 = (float4*)(sout + (2 * hl + 1) * (2 * S)) + 2 * wq;
    srow0[0] = r0a;
    srow0[1] = r0b;
    srow1[0] = r1a;
    srow1[1] = r1b;

    __syncthreads();

    if (t == 0) {
        asm volatile("fence.proxy.async.shared::cta;" ::: "memory");
        // output rows 8*k2 .. 8*k2+8  (32KB contiguous)
        float* gdst = out + ((size_t)n * 2 * S + (size_t)8 * k2) * (2 * S);
        asm volatile(
            "cp.async.bulk.global.shared::cta.bulk_group [%0], [%1], %2;"
            :: "l"(gdst), "r"(smem_u32(sout)),
               "r"((unsigned)(8 * 2 * S * sizeof(float)))
            : "memory");
        asm volatile("cp.async.bulk.commit_group;" ::: "memory");
        asm volatile("cp.async.bulk.wait_group 0;" ::: "memory");
    }
}

extern "C" void kernel_launch(void* const* d_in, const int* in_sizes, int n_in,
                              void* d_out, int out_size) {
    const float* x = (const float*)d_in[0];
    float* out = (float*)d_out;
    // one CTA per (n, row-quad): 32 * 128 = 4096 CTAs
    haar_recon_kernel<<<NIMG * (S / 4), 512>>>(x, out);
}